// round 16
// baseline (speedup 1.0000x reference)
#include <cuda_runtime.h>

// image [1,128,128,512] f32 NHWC, RoI [N,4] f32 (cx,cy,w,h), POOL=7, STRIDE=16.
#define POOL    7
#define HH      128
#define WW      128
#define CC      512
#define NMAX    1024
#define CPC_MAX 96          // max cells per CTA chunk (smem: 96*32B = 3KB)

// Pinned vector load: asm volatile cannot be sunk/reordered by ptxas, and its
// outputs are forcibly live -> the register double-buffer survives compilation.
__device__ __forceinline__ float4 ldg_pin(const float4* p)
{
    float4 v;
    asm volatile("ld.global.nc.v4.f32 {%0,%1,%2,%3}, [%4];"
                 : "=f"(v.x), "=f"(v.y), "=f"(v.z), "=f"(v.w)
                 : "l"(p));
    return v;
}

// ---------------------------------------------------------------------------
// Single fused kernel, one wave of persistent CTAs (148 x 4 = 592).
//   Phase A: threads 0..cpc-1 compute their cell's bilinear params into smem.
//   Phase B: PING-PONG pinned pipeline, unrolled 2x so buffer rotation is
//            compile-time register renaming (R15's rotating version spent
//            ~24 MOVs/iter shuffling a1->a0 etc. — issue-overhead bound at
//            47.5% issue). Offsets die at issue time; weights are LDS-read
//            at consume time. Live state ~= 32 payload regs + addresses.
// ---------------------------------------------------------------------------
__global__ __launch_bounds__(256, 4)
void roi_pool_fused(const float* __restrict__ img, const float* __restrict__ roi,
                    float* __restrict__ out, int totalCells, int cpc)
{
    __shared__ int4   s_off[CPC_MAX];   // corner offsets, float4 units
    __shared__ float4 s_w  [CPC_MAX];   // bilinear weights

    const int base = blockIdx.x * cpc;
    const int tid  = threadIdx.x;

    if (base >= totalCells) return;

    // ---------------- Phase A: per-cell params into smem ----------------
    if (tid < cpc) {
        int cell = base + tid;
        if (cell < totalCells) {
            int n   = cell / (POOL * POOL);
            int rem = cell - n * (POOL * POOL);
            int py  = rem / POOL;
            int px  = rem - py * POOL;

            const float inv_stride = 1.0f / 16.0f;
            float cx = roi[n * 4 + 0];
            float cy = roi[n * 4 + 1];
            float w  = roi[n * 4 + 2];
            float h  = roi[n * 4 + 3];

            float r  = rintf((cx - 0.5f * w) * inv_stride);   // x start (col)
            float c  = rintf((cy - 0.5f * h) * inv_stride);   // y start (row)
            float wq = fmaxf(rintf(w * inv_stride), 1.0f);
            float hq = fmaxf(rintf(h * inv_stride), 1.0f);

            // y axis (rows, limit HH)
            float gy  = (py + 0.5f) / (float)POOL;
            float sy  = fminf(fmaxf(gy * hq - 0.5f, 0.0f), hq - 1.0f);
            float fy0 = floorf(sy);
            float ly  = sy - fy0;
            float fy1 = fminf(fy0 + 1.0f, hq - 1.0f);
            int iy0 = (int)fminf(fmaxf(c + fy0, 0.0f), (float)(HH - 1));
            int iy1 = (int)fminf(fmaxf(c + fy1, 0.0f), (float)(HH - 1));

            // x axis (cols, limit WW)
            float gx  = (px + 0.5f) / (float)POOL;
            float sx  = fminf(fmaxf(gx * wq - 0.5f, 0.0f), wq - 1.0f);
            float fx0 = floorf(sx);
            float lx  = sx - fx0;
            float fx1 = fminf(fx0 + 1.0f, wq - 1.0f);
            int ix0 = (int)fminf(fmaxf(r + fx0, 0.0f), (float)(WW - 1));
            int ix1 = (int)fminf(fmaxf(r + fx1, 0.0f), (float)(WW - 1));

            s_off[tid] = make_int4((iy0 * WW + ix0) * (CC / 4),
                                   (iy0 * WW + ix1) * (CC / 4),
                                   (iy1 * WW + ix0) * (CC / 4),
                                   (iy1 * WW + ix1) * (CC / 4));
            s_w[tid] = make_float4((1.0f - ly) * (1.0f - lx),
                                   (1.0f - ly) * lx,
                                   ly * (1.0f - lx),
                                   ly * lx);
        }
    }
    __syncthreads();

    // ---------------- Phase B: ping-pong pinned sweep ----------------
    const int lane = tid & 127;         // float4 lane within cell
    const int half = tid >> 7;          // which of 2 interleaved cells

    int nIter = totalCells - base;
    if (nIter > cpc) nIter = cpc;

    const float4* __restrict__ img4 = (const float4*)img;
    float4*       __restrict__ out4 = (float4*)out;

    int i = half;
    if (i >= nIter) return;

    // Prime buffer A with cell i.
    float4 aA, bA, cA, dA;
    {
        int4 o = s_off[i];
        aA = ldg_pin(img4 + o.x + lane);
        bA = ldg_pin(img4 + o.y + lane);
        cA = ldg_pin(img4 + o.z + lane);
        dA = ldg_pin(img4 + o.w + lane);
    }

    float4 aB, bB, cB, dB;

    while (true) {
        // ---- stage 1: issue B(i+2), consume A(i) ----
        int  j     = i + 2;
        bool moreB = j < nIter;
        if (moreB) {
            int4 o = s_off[j];
            aB = ldg_pin(img4 + o.x + lane);
            bB = ldg_pin(img4 + o.y + lane);
            cB = ldg_pin(img4 + o.z + lane);
            dB = ldg_pin(img4 + o.w + lane);
        }
        {
            float4 w = s_w[i];
            float4 r;
            r.x = w.x * aA.x + w.y * bA.x + w.z * cA.x + w.w * dA.x;
            r.y = w.x * aA.y + w.y * bA.y + w.z * cA.y + w.w * dA.y;
            r.z = w.x * aA.z + w.y * bA.z + w.z * cA.z + w.w * dA.z;
            r.w = w.x * aA.w + w.y * bA.w + w.z * cA.w + w.w * dA.w;
            __stcs(out4 + (size_t)(base + i) * (CC / 4) + lane, r);
        }
        if (!moreB) break;

        // ---- stage 2: issue A(i+4), consume B(i+2) ----
        int  k     = j + 2;
        bool moreA = k < nIter;
        if (moreA) {
            int4 o = s_off[k];
            aA = ldg_pin(img4 + o.x + lane);
            bA = ldg_pin(img4 + o.y + lane);
            cA = ldg_pin(img4 + o.z + lane);
            dA = ldg_pin(img4 + o.w + lane);
        }
        {
            float4 w = s_w[j];
            float4 r;
            r.x = w.x * aB.x + w.y * bB.x + w.z * cB.x + w.w * dB.x;
            r.y = w.x * aB.y + w.y * bB.y + w.z * cB.y + w.w * dB.y;
            r.z = w.x * aB.z + w.y * bB.z + w.z * cB.z + w.w * dB.z;
            r.w = w.x * aB.w + w.y * bB.w + w.z * cB.w + w.w * dB.w;
            __stcs(out4 + (size_t)(base + j) * (CC / 4) + lane, r);
        }
        if (!moreA) break;

        i = k;
    }
}

extern "C" void kernel_launch(void* const* d_in, const int* in_sizes, int n_in,
                              void* d_out, int out_size)
{
    const float* img = (const float*)d_in[0];   // [1,128,128,512] f32
    const float* roi = (const float*)d_in[1];   // [N,4] f32
    float*       out = (float*)d_out;           // [1,N,7,7,512] f32

    int N = in_sizes[1] / 4;
    if (N > NMAX) N = NMAX;
    int totalCells = N * POOL * POOL;

    int wave = 148 * 4;                          // one wave at occ=4
    int cpc  = (totalCells + wave - 1) / wave;   // cells per CTA chunk
    if (cpc > CPC_MAX) cpc = CPC_MAX;
    int grid = (totalCells + cpc - 1) / cpc;

    roi_pool_fused<<<grid, 256>>>(img, roi, out, totalCells, cpc);
}